// round 2
// baseline (speedup 1.0000x reference)
#include <cuda_runtime.h>

#define NN 100000
#define NE 1600000
#define NG 2048
#define HID 64
#define INF 14
#define EPSV 1e-5f

// ---------------- scratch (device globals; no allocation allowed) -----------
__device__ float4 g_A[NN * 16];      // 25.6 MB  (xw buffer)
__device__ float4 g_B[NN * 16];      // 25.6 MB  (h buffer)
__device__ float  g_dinv[NN];        // deg -> dinv in place
__device__ float  g_stats[2 * HID];  // [sum(64), sumsq(64)]
__device__ int    g_row[NE];
__device__ int    g_col[NE];
__device__ int    g_batch[NN];
__device__ int    g_is64;

// ---------------- index dtype detection + canonicalization ------------------
// If edge_index is int64 (values < 2^31), every odd int32 word is 0.
__global__ void detect_k(const int* __restrict__ ei32) {
    __shared__ int any;
    if (threadIdx.x == 0) any = 0;
    __syncthreads();
    long i = 1 + 2L * threadIdx.x * 1562;   // samples spread over first 3.2M int32s
    if (i < 2L * NE && ei32[i] != 0) any = 1;
    __syncthreads();
    if (threadIdx.x == 0) g_is64 = (any == 0) ? 1 : 0;
}

__global__ void convert_k(const void* __restrict__ ei, const void* __restrict__ bt) {
    long t0 = (long)blockIdx.x * blockDim.x + threadIdx.x;
    long stride = (long)gridDim.x * blockDim.x;
    if (g_is64) {
        const long long* e = (const long long*)ei;
        const long long* b = (const long long*)bt;
        for (long i = t0; i < NE; i += stride) { g_row[i] = (int)e[i]; g_col[i] = (int)e[NE + i]; }
        for (long i = t0; i < NN; i += stride) g_batch[i] = (int)b[i];
    } else {
        const int* e = (const int*)ei;
        const int* b = (const int*)bt;
        for (long i = t0; i < NE; i += stride) { g_row[i] = e[i]; g_col[i] = e[NE + i]; }
        for (long i = t0; i < NN; i += stride) g_batch[i] = b[i];
    }
}

// ---------------- degree / normalization ------------------------------------
__global__ void zero_deg_k() {
    int i = blockIdx.x * blockDim.x + threadIdx.x;
    if (i < NN) g_dinv[i] = 0.f;
}
__global__ void deg_k(const float* __restrict__ w) {
    long t = (long)blockIdx.x * blockDim.x + threadIdx.x;
    if (t < NE) atomicAdd(&g_dinv[g_col[t]], w[t]);
}
__global__ void dinv_k() {
    int i = blockIdx.x * blockDim.x + threadIdx.x;
    if (i < NN) g_dinv[i] = rsqrtf(g_dinv[i] + 1.f);
}

// ---------------- dense xw = h @ W (K = 14 or 64, out = 64) -----------------
template <int K>
__global__ void xw_k(const float* __restrict__ x, const float* __restrict__ W,
                     float4* __restrict__ out) {
    __shared__ float Ws[K * HID];
    __shared__ float Xs[4][K];
    int tid = threadIdx.x;  // 256
    for (int i = tid; i < K * HID; i += 256) Ws[i] = W[i];
    int node0 = blockIdx.x * 4;
    for (int i = tid; i < 4 * K; i += 256) {
        int nn = node0 + i / K;
        Xs[i / K][i % K] = (nn < NN) ? x[(long)nn * K + (i % K)] : 0.f;
    }
    __syncthreads();
    int node = node0 + tid / HID;
    int o = tid % HID;
    if (node < NN) {
        float acc = 0.f;
#pragma unroll
        for (int k = 0; k < K; k++) acc = fmaf(Xs[tid / HID][k], Ws[k * HID + o], acc);
        ((float*)out)[(long)node * HID + o] = acc;
    }
}

// ---------------- out = dinv^2 * xw + b  (self-loop term + bias) ------------
__global__ void agginit_k(const float4* __restrict__ xw, float4* __restrict__ out,
                          const float4* __restrict__ b4) {
    long t = (long)blockIdx.x * 256 + threadIdx.x;
    if (t >= (long)NN * 16) return;
    int node = (int)(t >> 4);
    int q = (int)(t & 15);
    float d = g_dinv[node];
    float s = d * d;
    float4 v = xw[t];
    float4 bb = b4[q];
    out[t] = make_float4(fmaf(s, v.x, bb.x), fmaf(s, v.y, bb.y),
                         fmaf(s, v.z, bb.z), fmaf(s, v.w, bb.w));
}

// ---------------- edge scatter: out[col] += norm * xw[row] ------------------
__global__ void scatter_k(const float4* __restrict__ xw, float4* __restrict__ out,
                          const float* __restrict__ w) {
    long t = (long)blockIdx.x * 256 + threadIdx.x;
    long e = t >> 4;
    int q = (int)(t & 15);
    if (e >= NE) return;
    int r = g_row[e], c = g_col[e];
    float nrm = g_dinv[r] * w[e] * g_dinv[c];
    float4 v = xw[(long)r * 16 + q];
    float4 a = make_float4(nrm * v.x, nrm * v.y, nrm * v.z, nrm * v.w);
    atomicAdd(&out[(long)c * 16 + q], a);   // RED.128, sm_90+
}

// ---------------- batchnorm stats + apply -----------------------------------
__global__ void zero_stats_k() {
    if (threadIdx.x < 2 * HID) g_stats[threadIdx.x] = 0.f;
}
__global__ void stats_k(const float* __restrict__ h) {
    __shared__ float ss[2 * HID];
    int tid = threadIdx.x;  // 256
    if (tid < 2 * HID) ss[tid] = 0.f;
    __syncthreads();
    int f = tid & 63;
    float s = 0.f, s2 = 0.f;
    for (long n = (long)blockIdx.x * 4 + tid / 64; n < NN; n += (long)gridDim.x * 4) {
        float v = h[n * 64 + f];
        s += v;
        s2 = fmaf(v, v, s2);
    }
    atomicAdd(&ss[f], s);
    atomicAdd(&ss[64 + f], s2);
    __syncthreads();
    if (tid < 2 * HID) atomicAdd(&g_stats[tid], ss[tid]);
}
__global__ void bnrelu_k(float4* __restrict__ h, const float* __restrict__ g,
                         const float* __restrict__ bt) {
    long t = (long)blockIdx.x * 256 + threadIdx.x;
    if (t >= (long)NN * 16) return;
    int f0 = (int)(t & 15) * 4;
    float4 v = h[t];
    float r[4] = {v.x, v.y, v.z, v.w};
#pragma unroll
    for (int j = 0; j < 4; j++) {
        int f = f0 + j;
        float mean = g_stats[f] * (1.f / NN);
        float var = g_stats[64 + f] * (1.f / NN) - mean * mean;
        float y = g[f] * (r[j] - mean) * rsqrtf(var + EPSV) + bt[f];
        r[j] = fmaxf(y, 0.f);
    }
    h[t] = make_float4(r[0], r[1], r[2], r[3]);
}

// ---------------- graph pooling + FC ----------------------------------------
__global__ void zero4_k(float4* __restrict__ p, long n) {
    long t = (long)blockIdx.x * blockDim.x + threadIdx.x;
    if (t < n) p[t] = make_float4(0.f, 0.f, 0.f, 0.f);
}
__global__ void seg_k(const float4* __restrict__ h, float4* __restrict__ ge) {
    long t = (long)blockIdx.x * 256 + threadIdx.x;
    if (t >= (long)NN * 16) return;
    int node = (int)(t >> 4);
    int q = (int)(t & 15);
    int g = g_batch[node];
    atomicAdd(&ge[(long)g * 16 + q], h[t]);
}
__global__ void fc_k(const float* __restrict__ ge, const float* __restrict__ W,
                     const float* __restrict__ b, float* __restrict__ out) {
    int t = blockIdx.x * blockDim.x + threadIdx.x;
    if (t >= NG * 2) return;
    int g = t >> 1, c = t & 1;
    float acc = b[c];
#pragma unroll
    for (int f = 0; f < 64; f++) acc = fmaf(ge[g * 64 + f], W[f * 2 + c], acc);
    out[t] = acc;
}

// ---------------- orchestration ----------------------------------------------
extern "C" void kernel_launch(void* const* d_in, const int* in_sizes, int n_in,
                              void* d_out, int out_size) {
    const float* x  = (const float*)d_in[0];
    const void*  ei = d_in[1];
    const void*  bt = d_in[2];
    const float* ew = (const float*)d_in[3];
    const float* W1 = (const float*)d_in[4];
    const float* b1 = (const float*)d_in[5];
    const float* W2 = (const float*)d_in[6];
    const float* b2 = (const float*)d_in[7];
    const float* W3 = (const float*)d_in[8];
    const float* b3 = (const float*)d_in[9];
    const float* g1 = (const float*)d_in[10];
    const float* t1 = (const float*)d_in[11];
    const float* g2 = (const float*)d_in[12];
    const float* t2 = (const float*)d_in[13];
    const float* g3 = (const float*)d_in[14];
    const float* t3 = (const float*)d_in[15];
    const float* fcW = (const float*)d_in[16];
    const float* fcb = (const float*)d_in[17];

    float* out      = (float*)d_out;                 // [2048*2]
    float* node_out = out + NG * 2;                  // [100000*64]
    float* gemb     = node_out + (long)NN * HID;     // [2048*64]

    float4 *A, *B;
    cudaGetSymbolAddress((void**)&A, g_A);
    cudaGetSymbolAddress((void**)&B, g_B);
    float4* NO = (float4*)node_out;

    const int NB_N   = (NN + 255) / 256;             // 391
    const int NB_E   = (NE + 255) / 256;             // 6250
    const int NB_NF4 = (int)(((long)NN * 16 + 255) / 256);  // 6250
    const int NB_EF4 = (int)(((long)NE * 16 + 255) / 256);  // 100000

    // index canonicalization + degree
    detect_k<<<1, 1024>>>((const int*)ei);
    convert_k<<<2048, 256>>>(ei, bt);
    zero_deg_k<<<NB_N, 256>>>();
    deg_k<<<NB_E, 256>>>(ew);
    dinv_k<<<NB_N, 256>>>();

    // ---- layer 1: x(14) -> A ; agg A->B ; bnrelu(B)
    xw_k<INF><<<NN / 4, 256>>>(x, W1, A);
    agginit_k<<<NB_NF4, 256>>>(A, B, (const float4*)b1);
    scatter_k<<<NB_EF4, 256>>>(A, B, ew);
    zero_stats_k<<<1, 128>>>();
    stats_k<<<1024, 256>>>((const float*)B);
    bnrelu_k<<<NB_NF4, 256>>>(B, g1, t1);

    // ---- layer 2: B(64) -> A ; agg A->B ; bnrelu(B)
    xw_k<HID><<<NN / 4, 256>>>((const float*)B, W2, A);
    agginit_k<<<NB_NF4, 256>>>(A, B, (const float4*)b2);
    scatter_k<<<NB_EF4, 256>>>(A, B, ew);
    zero_stats_k<<<1, 128>>>();
    stats_k<<<1024, 256>>>((const float*)B);
    bnrelu_k<<<NB_NF4, 256>>>(B, g2, t2);

    // ---- layer 3: B(64) -> A ; agg A->node_out ; bnrelu(node_out)
    xw_k<HID><<<NN / 4, 256>>>((const float*)B, W3, A);
    agginit_k<<<NB_NF4, 256>>>(A, NO, (const float4*)b3);
    scatter_k<<<NB_EF4, 256>>>(A, NO, ew);
    zero_stats_k<<<1, 128>>>();
    stats_k<<<1024, 256>>>(node_out);
    bnrelu_k<<<NB_NF4, 256>>>(NO, g3, t3);

    // ---- pooling + fc
    zero4_k<<<(NG * 16 + 255) / 256, 256>>>((float4*)gemb, (long)NG * 16);
    seg_k<<<NB_NF4, 256>>>(NO, (float4*)gemb);
    fc_k<<<(NG * 2 + 255) / 256, 256>>>(gemb, fcW, fcb, out);
}

// round 3
// speedup vs baseline: 1.3557x; 1.3557x over previous
#include <cuda_runtime.h>

#define NN 100000
#define NE 1600000
#define NG 2048
#define HID 64
#define INF 14
#define EPSV 1e-5f
#define SCAN_B 1024
#define SCAN_NB ((NN + SCAN_B - 1) / SCAN_B)   // 98

// ---------------- scratch (device globals; no allocation allowed) -----------
__device__ float4 g_A[NN * 16];      // xw buffer
__device__ float4 g_B[NN * 16];      // h buffer
__device__ float  g_dinv[NN];        // deg (w-sum) -> dinv in place
__device__ float  g_stats[2 * HID];  // [sum(64), sumsq(64)]
__device__ float  g_bnc[2 * HID];    // bn affine coefs [a(64), c(64)]
__device__ int    g_row[NE];
__device__ int    g_col[NE];
__device__ int    g_srow[NE];        // CSR-sorted source rows
__device__ float  g_snorm[NE];       // CSR-sorted edge norms
__device__ int    g_cnt[NN];         // in-degree counts
__device__ int    g_off[NN + 1];     // CSR offsets
__device__ int    g_cur[NN];         // scatter cursors
__device__ int    g_bsum[SCAN_NB];
__device__ int    g_batch[NN];
__device__ int    g_is64;

// ---------------- index dtype detection -------------------------------------
__global__ void detect_k(const int* __restrict__ ei32) {
    __shared__ int any;
    if (threadIdx.x == 0) any = 0;
    __syncthreads();
    long i = 1 + 2L * threadIdx.x * 1562;
    if (i < 2L * NE && ei32[i] != 0) any = 1;
    __syncthreads();
    if (threadIdx.x == 0) g_is64 = (any == 0) ? 1 : 0;
}

__global__ void zero_nd_k() {
    int i = blockIdx.x * blockDim.x + threadIdx.x;
    if (i < NN) { g_cnt[i] = 0; g_dinv[i] = 0.f; }
}

// convert indices to int32 + histogram (count + weighted degree)
__global__ void convert_hist_k(const void* __restrict__ ei, const void* __restrict__ bt,
                               const float* __restrict__ w) {
    long t0 = (long)blockIdx.x * blockDim.x + threadIdx.x;
    long stride = (long)gridDim.x * blockDim.x;
    if (g_is64) {
        const long long* e = (const long long*)ei;
        const long long* b = (const long long*)bt;
        for (long i = t0; i < NE; i += stride) {
            int r = (int)e[i], c = (int)e[NE + i];
            g_row[i] = r; g_col[i] = c;
            atomicAdd(&g_cnt[c], 1);
            atomicAdd(&g_dinv[c], w[i]);
        }
        for (long i = t0; i < NN; i += stride) g_batch[i] = (int)b[i];
    } else {
        const int* e = (const int*)ei;
        const int* b = (const int*)bt;
        for (long i = t0; i < NE; i += stride) {
            int r = e[i], c = e[NE + i];
            g_row[i] = r; g_col[i] = c;
            atomicAdd(&g_cnt[c], 1);
            atomicAdd(&g_dinv[c], w[i]);
        }
        for (long i = t0; i < NN; i += stride) g_batch[i] = b[i];
    }
}

__global__ void dinv_k() {
    int i = blockIdx.x * blockDim.x + threadIdx.x;
    if (i < NN) g_dinv[i] = rsqrtf(g_dinv[i] + 1.f);
}

// ---------------- 3-pass exclusive scan of g_cnt -> g_off -------------------
__global__ void scan1_k() {
    __shared__ int sh[256];
    int base = blockIdx.x * SCAN_B;
    int s = 0;
    for (int i = threadIdx.x; i < SCAN_B; i += 256) {
        int idx = base + i;
        s += (idx < NN) ? g_cnt[idx] : 0;
    }
    sh[threadIdx.x] = s;
    __syncthreads();
    for (int o = 128; o > 0; o >>= 1) {
        if (threadIdx.x < o) sh[threadIdx.x] += sh[threadIdx.x + o];
        __syncthreads();
    }
    if (threadIdx.x == 0) g_bsum[blockIdx.x] = sh[0];
}
__global__ void scan2_k() {
    __shared__ int sh[128];
    int t = threadIdx.x;
    int orig = (t < SCAN_NB) ? g_bsum[t] : 0;
    sh[t] = orig;
    __syncthreads();
    for (int o = 1; o < 128; o <<= 1) {
        int v = (t >= o) ? sh[t - o] : 0;
        __syncthreads();
        sh[t] += v;
        __syncthreads();
    }
    if (t < SCAN_NB) g_bsum[t] = sh[t] - orig;   // exclusive
    if (t == 127) g_off[NN] = sh[127];
}
__global__ void scan3_k() {
    __shared__ int sh[256];
    int base = blockIdx.x * SCAN_B;
    int i0 = base + threadIdx.x * 4;
    int vals[4];
    int tsum = 0;
#pragma unroll
    for (int k = 0; k < 4; k++) {
        int idx = i0 + k;
        vals[k] = (idx < NN) ? g_cnt[idx] : 0;
        tsum += vals[k];
    }
    sh[threadIdx.x] = tsum;
    __syncthreads();
    for (int o = 1; o < 256; o <<= 1) {
        int v = (threadIdx.x >= o) ? sh[threadIdx.x - o] : 0;
        __syncthreads();
        sh[threadIdx.x] += v;
        __syncthreads();
    }
    int excl = g_bsum[blockIdx.x] + sh[threadIdx.x] - tsum;
#pragma unroll
    for (int k = 0; k < 4; k++) {
        int idx = i0 + k;
        if (idx < NN) { g_off[idx] = excl; g_cur[idx] = excl; excl += vals[k]; }
    }
}

// scatter edges into CSR order, precompute norm once (shared by all 3 layers)
__global__ void fill_k(const float* __restrict__ w) {
    long e = (long)blockIdx.x * 256 + threadIdx.x;
    if (e >= NE) return;
    int r = g_row[e], c = g_col[e];
    int pos = atomicAdd(&g_cur[c], 1);
    g_srow[pos] = r;
    g_snorm[pos] = g_dinv[r] * w[e] * g_dinv[c];
}

// ---------------- dense xw = act(h) @ W  (optionally fused BN+ReLU on input) -
template <int K, bool BN>
__global__ void xw_k(const float* __restrict__ x, const float* __restrict__ W,
                     float4* __restrict__ out) {
    __shared__ float Ws[K * HID];
    __shared__ float Xs[4][K];
    __shared__ float As[BN ? K : 1], Cs[BN ? K : 1];
    int tid = threadIdx.x;  // 256
    for (int i = tid; i < K * HID; i += 256) Ws[i] = W[i];
    if (BN && tid < K) { As[tid] = g_bnc[tid]; Cs[tid] = g_bnc[64 + tid]; }
    __syncthreads();
    int node0 = blockIdx.x * 4;
    for (int i = tid; i < 4 * K; i += 256) {
        int nn = node0 + i / K;
        int f = i % K;
        float v = (nn < NN) ? x[(long)nn * K + f] : 0.f;
        if (BN) v = fmaxf(fmaf(As[f], v, Cs[f]), 0.f);
        Xs[i / K][f] = v;
    }
    __syncthreads();
    int node = node0 + tid / HID;
    int o = tid % HID;
    if (node < NN) {
        float acc = 0.f;
#pragma unroll
        for (int k = 0; k < K; k++) acc = fmaf(Xs[tid / HID][k], Ws[k * HID + o], acc);
        ((float*)out)[(long)node * HID + o] = acc;
    }
}

// ---------------- CSR gather: out[c] = dinv^2*xw[c] + b + sum(norm*xw[row]) -
__global__ void gather_k(const float4* __restrict__ xw, float4* __restrict__ out,
                         const float4* __restrict__ b4) {
    int node = blockIdx.x * 16 + (threadIdx.x >> 4);
    int q = threadIdx.x & 15;
    if (node >= NN) return;
    int start = g_off[node], end = g_off[node + 1];
    float d = g_dinv[node];
    float s = d * d;
    float4 v = xw[(long)node * 16 + q];
    float4 bb = b4[q];
    float4 acc = make_float4(fmaf(s, v.x, bb.x), fmaf(s, v.y, bb.y),
                             fmaf(s, v.z, bb.z), fmaf(s, v.w, bb.w));
    int j = start;
    for (; j + 1 < end; j += 2) {
        int r0 = g_srow[j], r1 = g_srow[j + 1];
        float n0 = g_snorm[j], n1 = g_snorm[j + 1];
        float4 v0 = xw[(long)r0 * 16 + q];
        float4 v1 = xw[(long)r1 * 16 + q];
        acc.x = fmaf(n0, v0.x, fmaf(n1, v1.x, acc.x));
        acc.y = fmaf(n0, v0.y, fmaf(n1, v1.y, acc.y));
        acc.z = fmaf(n0, v0.z, fmaf(n1, v1.z, acc.z));
        acc.w = fmaf(n0, v0.w, fmaf(n1, v1.w, acc.w));
    }
    if (j < end) {
        int r0 = g_srow[j];
        float n0 = g_snorm[j];
        float4 v0 = xw[(long)r0 * 16 + q];
        acc.x = fmaf(n0, v0.x, acc.x);
        acc.y = fmaf(n0, v0.y, acc.y);
        acc.z = fmaf(n0, v0.z, acc.z);
        acc.w = fmaf(n0, v0.w, acc.w);
    }
    out[(long)node * 16 + q] = acc;
}

// ---------------- batchnorm stats + coef ------------------------------------
__global__ void zero_stats_k() {
    if (threadIdx.x < 2 * HID) g_stats[threadIdx.x] = 0.f;
}
__global__ void stats_k(const float* __restrict__ h) {
    __shared__ float ss[2 * HID];
    int tid = threadIdx.x;  // 256
    if (tid < 2 * HID) ss[tid] = 0.f;
    __syncthreads();
    int f = tid & 63;
    float s = 0.f, s2 = 0.f;
    for (long n = (long)blockIdx.x * 4 + tid / 64; n < NN; n += (long)gridDim.x * 4) {
        float v = h[n * 64 + f];
        s += v;
        s2 = fmaf(v, v, s2);
    }
    atomicAdd(&ss[f], s);
    atomicAdd(&ss[64 + f], s2);
    __syncthreads();
    if (tid < 2 * HID) atomicAdd(&g_stats[tid], ss[tid]);
}
__global__ void coef_k(const float* __restrict__ g, const float* __restrict__ bt) {
    int f = threadIdx.x;
    if (f < HID) {
        float mean = g_stats[f] * (1.f / NN);
        float var = g_stats[64 + f] * (1.f / NN) - mean * mean;
        float a = g[f] * rsqrtf(var + EPSV);
        g_bnc[f] = a;
        g_bnc[64 + f] = bt[f] - mean * a;
    }
}

// ---------------- final: bn+relu apply, write node_out, pool to gemb --------
__global__ void zero4_k(float4* __restrict__ p, long n) {
    long t = (long)blockIdx.x * blockDim.x + threadIdx.x;
    if (t < n) p[t] = make_float4(0.f, 0.f, 0.f, 0.f);
}
__global__ void bnrelu_seg_k(const float4* __restrict__ h, float4* __restrict__ no,
                             float4* __restrict__ ge) {
    long t = (long)blockIdx.x * 256 + threadIdx.x;
    if (t >= (long)NN * 16) return;
    int node = (int)(t >> 4);
    int q = (int)(t & 15);
    int f0 = q * 4;
    float4 v = h[t];
    float r[4] = {v.x, v.y, v.z, v.w};
#pragma unroll
    for (int jj = 0; jj < 4; jj++) {
        int f = f0 + jj;
        r[jj] = fmaxf(fmaf(g_bnc[f], r[jj], g_bnc[64 + f]), 0.f);
    }
    float4 res = make_float4(r[0], r[1], r[2], r[3]);
    no[t] = res;
    atomicAdd(&ge[(long)g_batch[node] * 16 + q], res);
}

__global__ void fc_k(const float* __restrict__ ge, const float* __restrict__ W,
                     const float* __restrict__ b, float* __restrict__ out) {
    int t = blockIdx.x * blockDim.x + threadIdx.x;
    if (t >= NG * 2) return;
    int g = t >> 1, c = t & 1;
    float acc = b[c];
#pragma unroll
    for (int f = 0; f < 64; f++) acc = fmaf(ge[g * 64 + f], W[f * 2 + c], acc);
    out[t] = acc;
}

// ---------------- orchestration ----------------------------------------------
extern "C" void kernel_launch(void* const* d_in, const int* in_sizes, int n_in,
                              void* d_out, int out_size) {
    const float* x  = (const float*)d_in[0];
    const void*  ei = d_in[1];
    const void*  bt = d_in[2];
    const float* ew = (const float*)d_in[3];
    const float* W1 = (const float*)d_in[4];
    const float* b1 = (const float*)d_in[5];
    const float* W2 = (const float*)d_in[6];
    const float* b2 = (const float*)d_in[7];
    const float* W3 = (const float*)d_in[8];
    const float* b3 = (const float*)d_in[9];
    const float* g1 = (const float*)d_in[10];
    const float* t1 = (const float*)d_in[11];
    const float* g2 = (const float*)d_in[12];
    const float* t2 = (const float*)d_in[13];
    const float* g3 = (const float*)d_in[14];
    const float* t3 = (const float*)d_in[15];
    const float* fcW = (const float*)d_in[16];
    const float* fcb = (const float*)d_in[17];

    float* out      = (float*)d_out;
    float* node_out = out + NG * 2;
    float* gemb     = node_out + (long)NN * HID;

    float4 *A, *B;
    cudaGetSymbolAddress((void**)&A, g_A);
    cudaGetSymbolAddress((void**)&B, g_B);
    float4* NO = (float4*)node_out;

    const int NB_N   = (NN + 255) / 256;                    // 391
    const int NB_E   = (NE + 255) / 256;                    // 6250
    const int NB_NF4 = (int)(((long)NN * 16 + 255) / 256);  // 6250
    const int NB_G16 = (NN + 15) / 16;                      // 6250

    // ---- index canonicalization + CSR build (once, reused by all 3 layers)
    detect_k<<<1, 1024>>>((const int*)ei);
    zero_nd_k<<<NB_N, 256>>>();
    convert_hist_k<<<2048, 256>>>(ei, bt, ew);
    dinv_k<<<NB_N, 256>>>();
    scan1_k<<<SCAN_NB, 256>>>();
    scan2_k<<<1, 128>>>();
    scan3_k<<<SCAN_NB, 256>>>();
    fill_k<<<NB_E, 256>>>(ew);

    // ---- layer 1
    xw_k<INF, false><<<NN / 4, 256>>>(x, W1, A);
    gather_k<<<NB_G16, 256>>>(A, B, (const float4*)b1);
    zero_stats_k<<<1, 128>>>();
    stats_k<<<1024, 256>>>((const float*)B);
    coef_k<<<1, 64>>>(g1, t1);

    // ---- layer 2 (BN+ReLU of layer1 fused into xw input)
    xw_k<HID, true><<<NN / 4, 256>>>((const float*)B, W2, A);
    gather_k<<<NB_G16, 256>>>(A, B, (const float4*)b2);
    zero_stats_k<<<1, 128>>>();
    stats_k<<<1024, 256>>>((const float*)B);
    coef_k<<<1, 64>>>(g2, t2);

    // ---- layer 3
    xw_k<HID, true><<<NN / 4, 256>>>((const float*)B, W3, A);
    gather_k<<<NB_G16, 256>>>(A, B, (const float4*)b3);
    zero_stats_k<<<1, 128>>>();
    stats_k<<<1024, 256>>>((const float*)B);
    coef_k<<<1, 64>>>(g3, t3);

    // ---- fused bn+relu apply + pooling, then fc
    zero4_k<<<(NG * 16 + 255) / 256, 256>>>((float4*)gemb, (long)NG * 16);
    bnrelu_seg_k<<<NB_NF4, 256>>>(B, NO, (float4*)gemb);
    fc_k<<<(NG * 2 + 255) / 256, 256>>>(gemb, fcW, fcb, out);
}

// round 4
// speedup vs baseline: 1.3580x; 1.0017x over previous
#include <cuda_runtime.h>
#include <cuda_fp16.h>

#define NN 100000
#define NE 1600000
#define NG 2048
#define HID 64
#define INF 14
#define EPSV 1e-5f
#define SCAN_B 1024
#define SCAN_NB ((NN + SCAN_B - 1) / SCAN_B)   // 98

// ---------------- scratch (device globals; no allocation allowed) -----------
__device__ __half2 g_Ah[NN * 32];    // 12.8 MB xw buffer (fp16)
__device__ float4  g_B[NN * 16];     // 25.6 MB h buffer (fp32)
__device__ float   g_dinv[NN];
__device__ float   g_stats[2 * HID]; // [sum(64), sumsq(64)]
__device__ float   g_bnc[2 * HID];   // bn affine coefs [a(64), c(64)]
__device__ int     g_row[NE];
__device__ int     g_col[NE];
__device__ int     g_srow[NE];       // CSR-sorted source rows
__device__ float   g_snorm[NE];      // CSR-sorted edge norms
__device__ int     g_cnt[NN];
__device__ int     g_off[NN + 1];
__device__ int     g_cur[NN];
__device__ int     g_bsum[SCAN_NB];
__device__ int     g_batch[NN];
__device__ int     g_is64;

// ---------------- index dtype detection -------------------------------------
__global__ void detect_k(const int* __restrict__ ei32) {
    __shared__ int any;
    if (threadIdx.x == 0) any = 0;
    __syncthreads();
    long i = 1 + 2L * threadIdx.x * 1562;
    if (i < 2L * NE && ei32[i] != 0) any = 1;
    __syncthreads();
    if (threadIdx.x == 0) g_is64 = (any == 0) ? 1 : 0;
}

__global__ void zero_nd_k() {
    int i = blockIdx.x * blockDim.x + threadIdx.x;
    if (i < NN) { g_cnt[i] = 0; g_dinv[i] = 0.f; }
    if (i < 2 * HID) g_stats[i] = 0.f;
}

// convert indices to int32 + histogram (count + weighted degree)
__global__ void convert_hist_k(const void* __restrict__ ei, const void* __restrict__ bt,
                               const float* __restrict__ w) {
    long t0 = (long)blockIdx.x * blockDim.x + threadIdx.x;
    long stride = (long)gridDim.x * blockDim.x;
    if (g_is64) {
        const long long* e = (const long long*)ei;
        const long long* b = (const long long*)bt;
        for (long i = t0; i < NE; i += stride) {
            int r = (int)e[i], c = (int)e[NE + i];
            g_row[i] = r; g_col[i] = c;
            atomicAdd(&g_cnt[c], 1);
            atomicAdd(&g_dinv[c], w[i]);
        }
        for (long i = t0; i < NN; i += stride) g_batch[i] = (int)b[i];
    } else {
        const int* e = (const int*)ei;
        const int* b = (const int*)bt;
        for (long i = t0; i < NE; i += stride) {
            int r = e[i], c = e[NE + i];
            g_row[i] = r; g_col[i] = c;
            atomicAdd(&g_cnt[c], 1);
            atomicAdd(&g_dinv[c], w[i]);
        }
        for (long i = t0; i < NN; i += stride) g_batch[i] = b[i];
    }
}

__global__ void dinv_k() {
    int i = blockIdx.x * blockDim.x + threadIdx.x;
    if (i < NN) g_dinv[i] = rsqrtf(g_dinv[i] + 1.f);
}

// ---------------- 3-pass exclusive scan of g_cnt -> g_off -------------------
__global__ void scan1_k() {
    __shared__ int sh[256];
    int base = blockIdx.x * SCAN_B;
    int s = 0;
    for (int i = threadIdx.x; i < SCAN_B; i += 256) {
        int idx = base + i;
        s += (idx < NN) ? g_cnt[idx] : 0;
    }
    sh[threadIdx.x] = s;
    __syncthreads();
    for (int o = 128; o > 0; o >>= 1) {
        if (threadIdx.x < o) sh[threadIdx.x] += sh[threadIdx.x + o];
        __syncthreads();
    }
    if (threadIdx.x == 0) g_bsum[blockIdx.x] = sh[0];
}
__global__ void scan2_k() {
    __shared__ int sh[128];
    int t = threadIdx.x;
    int orig = (t < SCAN_NB) ? g_bsum[t] : 0;
    sh[t] = orig;
    __syncthreads();
    for (int o = 1; o < 128; o <<= 1) {
        int v = (t >= o) ? sh[t - o] : 0;
        __syncthreads();
        sh[t] += v;
        __syncthreads();
    }
    if (t < SCAN_NB) g_bsum[t] = sh[t] - orig;
    if (t == 127) g_off[NN] = sh[127];
}
__global__ void scan3_k() {
    __shared__ int sh[256];
    int base = blockIdx.x * SCAN_B;
    int i0 = base + threadIdx.x * 4;
    int vals[4];
    int tsum = 0;
#pragma unroll
    for (int k = 0; k < 4; k++) {
        int idx = i0 + k;
        vals[k] = (idx < NN) ? g_cnt[idx] : 0;
        tsum += vals[k];
    }
    sh[threadIdx.x] = tsum;
    __syncthreads();
    for (int o = 1; o < 256; o <<= 1) {
        int v = (threadIdx.x >= o) ? sh[threadIdx.x - o] : 0;
        __syncthreads();
        sh[threadIdx.x] += v;
        __syncthreads();
    }
    int excl = g_bsum[blockIdx.x] + sh[threadIdx.x] - tsum;
#pragma unroll
    for (int k = 0; k < 4; k++) {
        int idx = i0 + k;
        if (idx < NN) { g_off[idx] = excl; g_cur[idx] = excl; excl += vals[k]; }
    }
}

__global__ void fill_k(const float* __restrict__ w) {
    long e = (long)blockIdx.x * 256 + threadIdx.x;
    if (e >= NE) return;
    int r = g_row[e], c = g_col[e];
    int pos = atomicAdd(&g_cur[c], 1);
    g_srow[pos] = r;
    g_snorm[pos] = g_dinv[r] * w[e] * g_dinv[c];
}

// ---------------- dense xw = act(h) @ W -> fp16 out -------------------------
template <int K, bool BN>
__global__ void xw_k(const float* __restrict__ x, const float* __restrict__ W,
                     __half2* __restrict__ outh) {
    __shared__ float Ws[K * HID];
    __shared__ float Xs[4][K];
    __shared__ float As[BN ? K : 1], Cs[BN ? K : 1];
    int tid = threadIdx.x;  // 256
    for (int i = tid; i < K * HID; i += 256) Ws[i] = W[i];
    if (BN && tid < K) { As[tid] = g_bnc[tid]; Cs[tid] = g_bnc[64 + tid]; }
    __syncthreads();
    int node0 = blockIdx.x * 4;
    for (int i = tid; i < 4 * K; i += 256) {
        int nn = node0 + i / K;
        int f = i % K;
        float v = (nn < NN) ? x[(long)nn * K + f] : 0.f;
        if (BN) v = fmaxf(fmaf(As[f], v, Cs[f]), 0.f);
        Xs[i / K][f] = v;
    }
    __syncthreads();
    int node = node0 + tid / HID;
    int o = tid % HID;
    float acc = 0.f;
#pragma unroll
    for (int k = 0; k < K; k++) acc = fmaf(Xs[tid / HID][k], Ws[k * HID + o], acc);
    float hi = __shfl_down_sync(0xffffffffu, acc, 1);
    if (node < NN && (o & 1) == 0)
        outh[(long)node * 32 + (o >> 1)] = __floats2half2_rn(acc, hi);
}

// ---- CSR gather (fp16 in, fp32 out) + fused BN-stats accumulation ----------
// 8 lanes/node, 32 nodes/block, grid = NN/32 = 3125 exactly.
__global__ void gatherh_k(const uint4* __restrict__ xw, float* __restrict__ out,
                          const float* __restrict__ b) {
    __shared__ float sm[2 * HID];
    int tid = threadIdx.x;  // 256
    if (tid < 2 * HID) sm[tid] = 0.f;
    __syncthreads();

    int node = blockIdx.x * 32 + (tid >> 3);
    int q = tid & 7;                       // features [q*8, q*8+8)
    int start = g_off[node], end = g_off[node + 1];
    float d = g_dinv[node];
    float s = d * d;

    float acc[8];
    {
        uint4 sv = xw[(long)node * 8 + q];
        const __half2* h2 = (const __half2*)&sv;
#pragma unroll
        for (int k = 0; k < 4; k++) {
            float2 f = __half22float2(h2[k]);
            acc[2 * k]     = fmaf(s, f.x, b[q * 8 + 2 * k]);
            acc[2 * k + 1] = fmaf(s, f.y, b[q * 8 + 2 * k + 1]);
        }
    }
    int j = start;
    for (; j + 1 < end; j += 2) {
        int r0 = g_srow[j], r1 = g_srow[j + 1];
        float n0 = g_snorm[j], n1 = g_snorm[j + 1];
        uint4 v0 = xw[(long)r0 * 8 + q];
        uint4 v1 = xw[(long)r1 * 8 + q];
        const __half2* a0 = (const __half2*)&v0;
        const __half2* a1 = (const __half2*)&v1;
#pragma unroll
        for (int k = 0; k < 4; k++) {
            float2 f0 = __half22float2(a0[k]);
            float2 f1 = __half22float2(a1[k]);
            acc[2 * k]     = fmaf(n0, f0.x, fmaf(n1, f1.x, acc[2 * k]));
            acc[2 * k + 1] = fmaf(n0, f0.y, fmaf(n1, f1.y, acc[2 * k + 1]));
        }
    }
    if (j < end) {
        int r0 = g_srow[j];
        float n0 = g_snorm[j];
        uint4 v0 = xw[(long)r0 * 8 + q];
        const __half2* a0 = (const __half2*)&v0;
#pragma unroll
        for (int k = 0; k < 4; k++) {
            float2 f0 = __half22float2(a0[k]);
            acc[2 * k]     = fmaf(n0, f0.x, acc[2 * k]);
            acc[2 * k + 1] = fmaf(n0, f0.y, acc[2 * k + 1]);
        }
    }
    // store h
    float4* o4 = (float4*)out;
    o4[(long)node * 16 + q * 2]     = make_float4(acc[0], acc[1], acc[2], acc[3]);
    o4[(long)node * 16 + q * 2 + 1] = make_float4(acc[4], acc[5], acc[6], acc[7]);

    // fused BN stats: reduce over the 4 nodes in this warp via shfl-xor,
    // then smem atomics, then one global flush per block.
    float ss[8], s2[8];
#pragma unroll
    for (int k = 0; k < 8; k++) { ss[k] = acc[k]; s2[k] = acc[k] * acc[k]; }
#pragma unroll
    for (int off = 8; off < 32; off <<= 1) {
#pragma unroll
        for (int k = 0; k < 8; k++) {
            ss[k] += __shfl_xor_sync(0xffffffffu, ss[k], off);
            s2[k] += __shfl_xor_sync(0xffffffffu, s2[k], off);
        }
    }
    if ((tid & 31) < 8) {
#pragma unroll
        for (int k = 0; k < 8; k++) {
            atomicAdd(&sm[q * 8 + k], ss[k]);
            atomicAdd(&sm[64 + q * 8 + k], s2[k]);
        }
    }
    __syncthreads();
    if (tid < 2 * HID) atomicAdd(&g_stats[tid], sm[tid]);
}

// ---------------- bn coefs (zeros stats for next layer) ---------------------
__global__ void coef_k(const float* __restrict__ g, const float* __restrict__ bt) {
    int f = threadIdx.x;
    if (f < HID) {
        float mean = g_stats[f] * (1.f / NN);
        float var = g_stats[64 + f] * (1.f / NN) - mean * mean;
        float a = g[f] * rsqrtf(var + EPSV);
        g_bnc[f] = a;
        g_bnc[64 + f] = bt[f] - mean * a;
        g_stats[f] = 0.f;
        g_stats[64 + f] = 0.f;
    }
}

// ---------------- final: bn+relu apply, write node_out, pool to gemb --------
__global__ void zero4_k(float4* __restrict__ p, long n) {
    long t = (long)blockIdx.x * blockDim.x + threadIdx.x;
    if (t < n) p[t] = make_float4(0.f, 0.f, 0.f, 0.f);
}
__global__ void bnrelu_seg_k(const float4* __restrict__ h, float4* __restrict__ no,
                             float4* __restrict__ ge) {
    long t = (long)blockIdx.x * 256 + threadIdx.x;
    if (t >= (long)NN * 16) return;
    int node = (int)(t >> 4);
    int q = (int)(t & 15);
    int f0 = q * 4;
    float4 v = h[t];
    float r[4] = {v.x, v.y, v.z, v.w};
#pragma unroll
    for (int jj = 0; jj < 4; jj++) {
        int f = f0 + jj;
        r[jj] = fmaxf(fmaf(g_bnc[f], r[jj], g_bnc[64 + f]), 0.f);
    }
    float4 res = make_float4(r[0], r[1], r[2], r[3]);
    no[t] = res;
    atomicAdd(&ge[(long)g_batch[node] * 16 + q], res);
}

__global__ void fc_k(const float* __restrict__ ge, const float* __restrict__ W,
                     const float* __restrict__ b, float* __restrict__ out) {
    int t = blockIdx.x * blockDim.x + threadIdx.x;
    if (t >= NG * 2) return;
    int g = t >> 1, c = t & 1;
    float acc = b[c];
#pragma unroll
    for (int f = 0; f < 64; f++) acc = fmaf(ge[g * 64 + f], W[f * 2 + c], acc);
    out[t] = acc;
}

// ---------------- orchestration ----------------------------------------------
extern "C" void kernel_launch(void* const* d_in, const int* in_sizes, int n_in,
                              void* d_out, int out_size) {
    const float* x  = (const float*)d_in[0];
    const void*  ei = d_in[1];
    const void*  bt = d_in[2];
    const float* ew = (const float*)d_in[3];
    const float* W1 = (const float*)d_in[4];
    const float* b1 = (const float*)d_in[5];
    const float* W2 = (const float*)d_in[6];
    const float* b2 = (const float*)d_in[7];
    const float* W3 = (const float*)d_in[8];
    const float* b3 = (const float*)d_in[9];
    const float* g1 = (const float*)d_in[10];
    const float* t1 = (const float*)d_in[11];
    const float* g2 = (const float*)d_in[12];
    const float* t2 = (const float*)d_in[13];
    const float* g3 = (const float*)d_in[14];
    const float* t3 = (const float*)d_in[15];
    const float* fcW = (const float*)d_in[16];
    const float* fcb = (const float*)d_in[17];

    float* out      = (float*)d_out;
    float* node_out = out + NG * 2;
    float* gemb     = node_out + (long)NN * HID;

    __half2* A;
    float4* B;
    cudaGetSymbolAddress((void**)&A, g_Ah);
    cudaGetSymbolAddress((void**)&B, g_B);
    float4* NO = (float4*)node_out;

    const int NB_N   = (NN + 255) / 256;                    // 391
    const int NB_E   = (NE + 255) / 256;                    // 6250
    const int NB_NF4 = (int)(((long)NN * 16 + 255) / 256);  // 6250
    const int NB_G32 = NN / 32;                             // 3125

    // ---- CSR build (once, reused by all 3 layers)
    detect_k<<<1, 1024>>>((const int*)ei);
    zero_nd_k<<<NB_N, 256>>>();
    convert_hist_k<<<2048, 256>>>(ei, bt, ew);
    dinv_k<<<NB_N, 256>>>();
    scan1_k<<<SCAN_NB, 256>>>();
    scan2_k<<<1, 128>>>();
    scan3_k<<<SCAN_NB, 256>>>();
    fill_k<<<NB_E, 256>>>(ew);

    // ---- layer 1
    xw_k<INF, false><<<NN / 4, 256>>>(x, W1, A);
    gatherh_k<<<NB_G32, 256>>>((const uint4*)A, (float*)B, b1);
    coef_k<<<1, 64>>>(g1, t1);

    // ---- layer 2 (BN+ReLU of layer1 fused into xw input)
    xw_k<HID, true><<<NN / 4, 256>>>((const float*)B, W2, A);
    gatherh_k<<<NB_G32, 256>>>((const uint4*)A, (float*)B, b2);
    coef_k<<<1, 64>>>(g2, t2);

    // ---- layer 3
    xw_k<HID, true><<<NN / 4, 256>>>((const float*)B, W3, A);
    gatherh_k<<<NB_G32, 256>>>((const uint4*)A, (float*)B, b3);
    coef_k<<<1, 64>>>(g3, t3);

    // ---- fused bn+relu apply + pooling, then fc
    zero4_k<<<(NG * 16 + 255) / 256, 256>>>((float4*)gemb, (long)NG * 16);
    bnrelu_seg_k<<<NB_NF4, 256>>>(B, NO, (float4*)gemb);
    fc_k<<<(NG * 2 + 255) / 256, 256>>>(gemb, fcW, fcb, out);
}